// round 1
// baseline (speedup 1.0000x reference)
#include <cuda_runtime.h>
#include <math.h>

#define NN 50000
#define NE 800000
#define MP 3
#define DF 256
#define NH 8
#define DOUTD 32
#define HIDN 128

// ---------------- scratch (static device memory; no allocation) ----------------
__device__ float g_feat[(size_t)MP * NN * DF];   // per-path projected features
__device__ float g_z[(size_t)MP * NN * DF];      // per-path GAT outputs (post-ELU)
__device__ float g_el[MP * NN * NH];
__device__ float g_er[MP * NN * NH];
__device__ int   g_cnt[MP * NN];
__device__ int   g_rowptr[MP * (NN + 1)];
__device__ int   g_rowcur[MP * NN];
__device__ int   g_ssrc[MP * NE];                // src ids sorted by dst (CSR)
__device__ float g_w[MP];
__device__ float g_beta[MP];

// ---------------- zero scratch that is accumulated into ----------------
__global__ void k_zero() {
    int i = blockIdx.x * blockDim.x + threadIdx.x;
    if (i < MP * NN) g_cnt[i] = 0;
    if (i < MP) g_w[i] = 0.f;
}

// ---------------- GEMM1: feat[m] = h @ W_gat[m]  (50000x128 @ 128x256) ----------------
__global__ __launch_bounds__(256) void k_gemm_feat(const float* __restrict__ A,
                                                   const float* __restrict__ Wg) {
    __shared__ float As[8][128];
    __shared__ float Bs[8][128];
    const int m = blockIdx.z;
    const float* B = Wg + (size_t)m * 128 * DF;
    float* C = g_feat + (size_t)m * NN * DF;
    const int rowBase = blockIdx.x * 128;
    const int colBase = blockIdx.y * 128;
    const int tid = threadIdx.x;
    const int tx = tid & 15, ty = tid >> 4;
    const int a_row = tid >> 1;
    const int a_k4  = (tid & 1) * 4;
    int agr = rowBase + a_row; if (agr >= NN) agr = NN - 1;
    const int b_krow = tid >> 5;
    const int b_col  = (tid & 31) * 4;

    float acc[8][8];
#pragma unroll
    for (int i = 0; i < 8; i++)
#pragma unroll
        for (int j = 0; j < 8; j++) acc[i][j] = 0.f;

    for (int kt = 0; kt < 128; kt += 8) {
        float4 av = *(const float4*)&A[(size_t)agr * 128 + kt + a_k4];
        float4 bv = *(const float4*)&B[(size_t)(kt + b_krow) * DF + colBase + b_col];
        __syncthreads();
        As[a_k4 + 0][a_row] = av.x; As[a_k4 + 1][a_row] = av.y;
        As[a_k4 + 2][a_row] = av.z; As[a_k4 + 3][a_row] = av.w;
        *(float4*)&Bs[b_krow][b_col] = bv;
        __syncthreads();
#pragma unroll
        for (int kk = 0; kk < 8; kk++) {
            float4 a0 = *(const float4*)&As[kk][ty * 8];
            float4 a1 = *(const float4*)&As[kk][ty * 8 + 4];
            float4 b0 = *(const float4*)&Bs[kk][tx * 8];
            float4 b1 = *(const float4*)&Bs[kk][tx * 8 + 4];
            float ar8[8] = {a0.x, a0.y, a0.z, a0.w, a1.x, a1.y, a1.z, a1.w};
            float br8[8] = {b0.x, b0.y, b0.z, b0.w, b1.x, b1.y, b1.z, b1.w};
#pragma unroll
            for (int i = 0; i < 8; i++)
#pragma unroll
                for (int j = 0; j < 8; j++) acc[i][j] += ar8[i] * br8[j];
        }
    }
#pragma unroll
    for (int i = 0; i < 8; i++) {
        int gr = rowBase + ty * 8 + i;
        if (gr < NN) {
            float4 v0 = {acc[i][0], acc[i][1], acc[i][2], acc[i][3]};
            float4 v1 = {acc[i][4], acc[i][5], acc[i][6], acc[i][7]};
            *(float4*)&C[(size_t)gr * DF + colBase + tx * 8]     = v0;
            *(float4*)&C[(size_t)gr * DF + colBase + tx * 8 + 4] = v1;
        }
    }
}

// ---------------- el/er: per (m,n,k) dot(feat_head, attn) ----------------
__global__ void k_eler(const float* __restrict__ al, const float* __restrict__ ar) {
    int idx = blockIdx.x * blockDim.x + threadIdx.x;
    if (idx >= MP * NN * NH) return;
    int m = idx / (NN * NH);
    int r = idx % (NN * NH);
    int n = r / NH, k = r % NH;
    const float* f   = g_feat + ((size_t)m * NN + n) * DF + k * DOUTD;
    const float* alp = al + (m * NH + k) * DOUTD;
    const float* arp = ar + (m * NH + k) * DOUTD;
    float sl = 0.f, sr = 0.f;
#pragma unroll
    for (int j = 0; j < DOUTD; j += 4) {
        float4 fv = *(const float4*)&f[j];
        float4 lv = *(const float4*)&alp[j];
        float4 rv = *(const float4*)&arp[j];
        sl += fv.x * lv.x + fv.y * lv.y + fv.z * lv.z + fv.w * lv.w;
        sr += fv.x * rv.x + fv.y * rv.y + fv.z * rv.z + fv.w * rv.w;
    }
    g_el[idx] = sl;
    g_er[idx] = sr;
}

// ---------------- CSR build: histogram, scan, scatter ----------------
__global__ void k_hist(const int* __restrict__ dst) {
    int i = blockIdx.x * blockDim.x + threadIdx.x;
    if (i >= MP * NE) return;
    int m = i / NE;
    atomicAdd(&g_cnt[m * NN + dst[i]], 1);
}

__global__ void k_scan() {
    const int m = blockIdx.x;
    __shared__ int ssum[1024];
    const int tid = threadIdx.x;
    const int CH = (NN + 1023) / 1024;
    int s0 = tid * CH, s1 = min(s0 + CH, NN);
    int acc = 0;
    for (int i = s0; i < s1; i++) acc += g_cnt[m * NN + i];
    ssum[tid] = acc;
    __syncthreads();
    if (tid == 0) {
        int run = 0;
        for (int j = 0; j < 1024; j++) { int v = ssum[j]; ssum[j] = run; run += v; }
        g_rowptr[m * (NN + 1) + NN] = run;
    }
    __syncthreads();
    int run = ssum[tid];
    for (int i = s0; i < s1; i++) {
        g_rowptr[m * (NN + 1) + i] = run;
        g_rowcur[m * NN + i] = run;
        run += g_cnt[m * NN + i];
    }
}

__global__ void k_scatter(const int* __restrict__ src, const int* __restrict__ dst) {
    int i = blockIdx.x * blockDim.x + threadIdx.x;
    if (i >= MP * NE) return;
    int m = i / NE;
    int t = dst[i];
    int pos = atomicAdd(&g_rowcur[m * NN + t], 1);
    g_ssrc[(size_t)m * NE + pos] = src[i];
}

// ---------------- per-(dst,path) segment softmax + aggregation ----------------
__global__ __launch_bounds__(256) void k_agg(const float* __restrict__ bias) {
    const int t = blockIdx.x, m = blockIdx.y;
    const int tid = threadIdx.x;
    const int rp  = g_rowptr[m * (NN + 1) + t];
    const int deg = g_rowptr[m * (NN + 1) + t + 1] - rp;
    __shared__ float s_mx[NH], s_dn[NH];
    const float* el = g_el + (size_t)m * NN * NH;
    const float* er = g_er + (size_t)m * NN * NH;
    const int* ss = g_ssrc + (size_t)m * NE + rp;

    if (tid < 32 && deg > 0) {
        float mx[NH], dn[NH], erk[NH];
#pragma unroll
        for (int k = 0; k < NH; k++) { mx[k] = -3.402823e38f; dn[k] = 0.f; erk[k] = er[t * NH + k]; }
        for (int j = tid; j < deg; j += 32) {
            int s = ss[j];
#pragma unroll
            for (int k = 0; k < NH; k++) {
                float e = el[s * NH + k] + erk[k];
                e = e > 0.f ? e : 0.2f * e;
                mx[k] = fmaxf(mx[k], e);
            }
        }
#pragma unroll
        for (int o = 16; o > 0; o >>= 1)
#pragma unroll
            for (int k = 0; k < NH; k++) mx[k] = fmaxf(mx[k], __shfl_xor_sync(0xffffffffu, mx[k], o));
        for (int j = tid; j < deg; j += 32) {
            int s = ss[j];
#pragma unroll
            for (int k = 0; k < NH; k++) {
                float e = el[s * NH + k] + erk[k];
                e = e > 0.f ? e : 0.2f * e;
                dn[k] += expf(e - mx[k]);
            }
        }
#pragma unroll
        for (int o = 16; o > 0; o >>= 1)
#pragma unroll
            for (int k = 0; k < NH; k++) dn[k] += __shfl_xor_sync(0xffffffffu, dn[k], o);
        if (tid == 0) {
#pragma unroll
            for (int k = 0; k < NH; k++) { s_mx[k] = mx[k]; s_dn[k] = dn[k]; }
        }
    }
    __syncthreads();

    const int k = tid >> 5, d = tid & 31;
    float acc = 0.f;
    if (deg > 0) {
        const float mk  = s_mx[k];
        const float inv = 1.f / (s_dn[k] + 1e-9f);
        const float erk = er[t * NH + k];
        const float* fb = g_feat + (size_t)m * NN * DF + k * DOUTD + d;
        for (int j = 0; j < deg; j++) {
            int s = ss[j];
            float e = el[s * NH + k] + erk;
            e = e > 0.f ? e : 0.2f * e;
            float alpha = expf(e - mk) * inv;
            acc += alpha * fb[(size_t)s * DF];
        }
    }
    acc += bias[m * DF + tid];
    float zv = acc > 0.f ? acc : expm1f(acc);
    g_z[((size_t)m * NN + t) * DF + tid] = zv;
}

// ---------------- GEMM2: fused semantic attention logits ----------------
// w[m] += sum over rows of ( tanh(z_row @ W1 + b1) . w2 )
__global__ __launch_bounds__(256) void k_gemm_sem(const float* __restrict__ W1,
                                                  const float* __restrict__ b1,
                                                  const float* __restrict__ w2) {
    __shared__ float As[8][128];
    __shared__ float Bs[8][128];
    __shared__ float s_w[MP];
    const int R = MP * NN;
    const int rowBase = blockIdx.x * 128;
    const int tid = threadIdx.x;
    const int tx = tid & 15, ty = tid >> 4;
    const int a_row = tid >> 1;
    const int a_k4  = (tid & 1) * 4;
    int agr = rowBase + a_row; if (agr >= R) agr = R - 1;
    const int b_krow = tid >> 5;
    const int b_col  = (tid & 31) * 4;
    const float* A = g_z;

    float acc[8][8];
#pragma unroll
    for (int i = 0; i < 8; i++)
#pragma unroll
        for (int j = 0; j < 8; j++) acc[i][j] = 0.f;

    for (int kt = 0; kt < 256; kt += 8) {
        float4 av = *(const float4*)&A[(size_t)agr * DF + kt + a_k4];
        float4 bv = *(const float4*)&W1[(size_t)(kt + b_krow) * HIDN + b_col];
        __syncthreads();
        As[a_k4 + 0][a_row] = av.x; As[a_k4 + 1][a_row] = av.y;
        As[a_k4 + 2][a_row] = av.z; As[a_k4 + 3][a_row] = av.w;
        *(float4*)&Bs[b_krow][b_col] = bv;
        __syncthreads();
#pragma unroll
        for (int kk = 0; kk < 8; kk++) {
            float4 a0 = *(const float4*)&As[kk][ty * 8];
            float4 a1 = *(const float4*)&As[kk][ty * 8 + 4];
            float4 b0 = *(const float4*)&Bs[kk][tx * 8];
            float4 b1v = *(const float4*)&Bs[kk][tx * 8 + 4];
            float ar8[8] = {a0.x, a0.y, a0.z, a0.w, a1.x, a1.y, a1.z, a1.w};
            float br8[8] = {b0.x, b0.y, b0.z, b0.w, b1v.x, b1v.y, b1v.z, b1v.w};
#pragma unroll
            for (int i = 0; i < 8; i++)
#pragma unroll
                for (int j = 0; j < 8; j++) acc[i][j] += ar8[i] * br8[j];
        }
    }

    if (tid < MP) s_w[tid] = 0.f;
    __syncthreads();

    float rsum[8];
#pragma unroll
    for (int i = 0; i < 8; i++) {
        float s = 0.f;
#pragma unroll
        for (int j = 0; j < 8; j++) {
            int col = tx * 8 + j;
            s += tanhf(acc[i][j] + b1[col]) * w2[col];
        }
#pragma unroll
        for (int o = 1; o < 16; o <<= 1) s += __shfl_xor_sync(0xffffffffu, s, o);
        rsum[i] = s;
    }
    if (tx == 0) {
#pragma unroll
        for (int i = 0; i < 8; i++) {
            int gr = rowBase + ty * 8 + i;
            if (gr < R) atomicAdd(&s_w[gr / NN], rsum[i]);
        }
    }
    __syncthreads();
    if (tid < MP) atomicAdd(&g_w[tid], s_w[tid]);
}

// ---------------- beta softmax (done once, not per-thread) ----------------
__global__ void k_beta() {
    if (threadIdx.x == 0 && blockIdx.x == 0) {
        float w0 = g_w[0] / (float)NN, w1 = g_w[1] / (float)NN, w2v = g_w[2] / (float)NN;
        float mx = fmaxf(w0, fmaxf(w1, w2v));
        float e0 = expf(w0 - mx), e1 = expf(w1 - mx), e2 = expf(w2v - mx);
        float s = e0 + e1 + e2;
        g_beta[0] = e0 / s; g_beta[1] = e1 / s; g_beta[2] = e2 / s;
    }
}

// ---------------- final weighted combine ----------------
__global__ void k_final(float* __restrict__ out) {
    int i = blockIdx.x * blockDim.x + threadIdx.x;
    if (i >= NN * DF) return;
    float b0 = g_beta[0], b1 = g_beta[1], b2 = g_beta[2];
    out[i] = b0 * g_z[i] + b1 * g_z[(size_t)NN * DF + i] + b2 * g_z[(size_t)2 * NN * DF + i];
}

extern "C" void kernel_launch(void* const* d_in, const int* in_sizes, int n_in,
                              void* d_out, int out_size) {
    const float* h  = (const float*)d_in[0];
    const float* Wg = (const float*)d_in[1];
    const float* al = (const float*)d_in[2];
    const float* ar = (const float*)d_in[3];
    const float* bg = (const float*)d_in[4];
    const float* W1 = (const float*)d_in[5];
    const float* b1 = (const float*)d_in[6];
    const float* w2 = (const float*)d_in[7];
    const int* src  = (const int*)d_in[8];
    const int* dst  = (const int*)d_in[9];
    float* out = (float*)d_out;

    k_zero<<<(MP * NN + 255) / 256, 256>>>();
    k_gemm_feat<<<dim3((NN + 127) / 128, DF / 128, MP), 256>>>(h, Wg);
    k_eler<<<(MP * NN * NH + 255) / 256, 256>>>(al, ar);
    k_hist<<<(MP * NE + 255) / 256, 256>>>(dst);
    k_scan<<<MP, 1024>>>();
    k_scatter<<<(MP * NE + 255) / 256, 256>>>(src, dst);
    k_agg<<<dim3(NN, MP), 256>>>(bg);
    k_gemm_sem<<<(MP * NN + 127) / 128, 256>>>(W1, b1, w2);
    k_beta<<<1, 1>>>();
    k_final<<<(NN * DF + 255) / 256, 256>>>(out);
}

// round 3
// speedup vs baseline: 1.3737x; 1.3737x over previous
#include <cuda_runtime.h>
#include <math.h>
#include <float.h>

#define NN 50000
#define NE 800000
#define MP 3
#define DF 256
#define NH 8
#define DOUTD 32
#define HIDN 128

// ---------------- scratch (static device memory; no allocation) ----------------
__device__ float g_feat[(size_t)MP * NN * DF];   // per-path projected features
__device__ float g_z[(size_t)MP * NN * DF];      // per-path GAT outputs (post-ELU)
__device__ float g_el[MP * NN * NH];
__device__ float g_er[MP * NN * NH];
__device__ int   g_cnt[MP * NN];
__device__ int   g_rowptr[MP * (NN + 1)];
__device__ int   g_rowcur[MP * NN];
__device__ int   g_ssrc[MP * NE];                // src ids sorted by dst (CSR)
__device__ float g_w[MP];
__device__ float g_beta[MP];

__global__ void k_zero() {
    int i = blockIdx.x * blockDim.x + threadIdx.x;
    if (i < MP * NN) g_cnt[i] = 0;
    if (i < MP) g_w[i] = 0.f;
}

// ---------------- GEMM1: feat[m] = h @ W_gat[m]  (50000x128 @ 128x256), double-buffered ----------------
__global__ __launch_bounds__(256) void k_gemm_feat(const float* __restrict__ A,
                                                   const float* __restrict__ Wg) {
    __shared__ float As[2][8][128];
    __shared__ float Bs[2][8][128];
    const int m = blockIdx.z;
    const float* B = Wg + (size_t)m * 128 * DF;
    float* C = g_feat + (size_t)m * NN * DF;
    const int rowBase = blockIdx.x * 128;
    const int colBase = blockIdx.y * 128;
    const int tid = threadIdx.x;
    const int tx = tid & 15, ty = tid >> 4;
    const int a_row = tid >> 1;
    const int a_k4  = (tid & 1) * 4;
    int agr = rowBase + a_row; if (agr >= NN) agr = NN - 1;
    const int b_krow = tid >> 5;
    const int b_col  = (tid & 31) * 4;

    float acc[8][8];
#pragma unroll
    for (int i = 0; i < 8; i++)
#pragma unroll
        for (int j = 0; j < 8; j++) acc[i][j] = 0.f;

    // prologue: load k-tile 0 into buffer 0
    {
        float4 av = *(const float4*)&A[(size_t)agr * 128 + a_k4];
        float4 bv = *(const float4*)&B[(size_t)b_krow * DF + colBase + b_col];
        As[0][a_k4 + 0][a_row] = av.x; As[0][a_k4 + 1][a_row] = av.y;
        As[0][a_k4 + 2][a_row] = av.z; As[0][a_k4 + 3][a_row] = av.w;
        *(float4*)&Bs[0][b_krow][b_col] = bv;
    }
    __syncthreads();

    int cur = 0;
    for (int kt = 0; kt < 128; kt += 8) {
        float4 av2, bv2;
        const bool more = (kt + 8 < 128);
        if (more) {
            av2 = *(const float4*)&A[(size_t)agr * 128 + kt + 8 + a_k4];
            bv2 = *(const float4*)&B[(size_t)(kt + 8 + b_krow) * DF + colBase + b_col];
        }
#pragma unroll
        for (int kk = 0; kk < 8; kk++) {
            float4 a0 = *(const float4*)&As[cur][kk][ty * 8];
            float4 a1 = *(const float4*)&As[cur][kk][ty * 8 + 4];
            float4 b0 = *(const float4*)&Bs[cur][kk][tx * 8];
            float4 b1 = *(const float4*)&Bs[cur][kk][tx * 8 + 4];
            float ar8[8] = {a0.x, a0.y, a0.z, a0.w, a1.x, a1.y, a1.z, a1.w};
            float br8[8] = {b0.x, b0.y, b0.z, b0.w, b1.x, b1.y, b1.z, b1.w};
#pragma unroll
            for (int i = 0; i < 8; i++)
#pragma unroll
                for (int j = 0; j < 8; j++) acc[i][j] += ar8[i] * br8[j];
        }
        if (more) {
            int nxt = cur ^ 1;
            As[nxt][a_k4 + 0][a_row] = av2.x; As[nxt][a_k4 + 1][a_row] = av2.y;
            As[nxt][a_k4 + 2][a_row] = av2.z; As[nxt][a_k4 + 3][a_row] = av2.w;
            *(float4*)&Bs[nxt][b_krow][b_col] = bv2;
            __syncthreads();
            cur = nxt;
        }
    }
#pragma unroll
    for (int i = 0; i < 8; i++) {
        int gr = rowBase + ty * 8 + i;
        if (gr < NN) {
            float4 v0 = {acc[i][0], acc[i][1], acc[i][2], acc[i][3]};
            float4 v1 = {acc[i][4], acc[i][5], acc[i][6], acc[i][7]};
            *(float4*)&C[(size_t)gr * DF + colBase + tx * 8]     = v0;
            *(float4*)&C[(size_t)gr * DF + colBase + tx * 8 + 4] = v1;
        }
    }
}

// ---------------- el/er: per (m,n,k) dot(feat_head, attn) ----------------
__global__ void k_eler(const float* __restrict__ al, const float* __restrict__ ar) {
    int idx = blockIdx.x * blockDim.x + threadIdx.x;
    if (idx >= MP * NN * NH) return;
    int m = idx / (NN * NH);
    int r = idx % (NN * NH);
    int n = r / NH, k = r % NH;
    const float* f   = g_feat + ((size_t)m * NN + n) * DF + k * DOUTD;
    const float* alp = al + (m * NH + k) * DOUTD;
    const float* arp = ar + (m * NH + k) * DOUTD;
    float sl = 0.f, sr = 0.f;
#pragma unroll
    for (int j = 0; j < DOUTD; j += 4) {
        float4 fv = *(const float4*)&f[j];
        float4 lv = *(const float4*)&alp[j];
        float4 rv = *(const float4*)&arp[j];
        sl += fv.x * lv.x + fv.y * lv.y + fv.z * lv.z + fv.w * lv.w;
        sr += fv.x * rv.x + fv.y * rv.y + fv.z * rv.z + fv.w * rv.w;
    }
    g_el[idx] = sl;
    g_er[idx] = sr;
}

// ---------------- CSR build: histogram, scan, scatter ----------------
__global__ void k_hist(const int* __restrict__ dst) {
    int i = blockIdx.x * blockDim.x + threadIdx.x;
    if (i >= MP * NE) return;
    int m = i / NE;
    atomicAdd(&g_cnt[m * NN + dst[i]], 1);
}

__global__ void k_scan() {
    const int m = blockIdx.x;
    __shared__ int ssum[1024];
    const int tid = threadIdx.x;
    const int CH = (NN + 1023) / 1024;
    int s0 = tid * CH, s1 = min(s0 + CH, NN);
    int acc = 0;
    for (int i = s0; i < s1; i++) acc += g_cnt[m * NN + i];
    ssum[tid] = acc;
    __syncthreads();
    if (tid == 0) {
        int run = 0;
        for (int j = 0; j < 1024; j++) { int v = ssum[j]; ssum[j] = run; run += v; }
        g_rowptr[m * (NN + 1) + NN] = run;
    }
    __syncthreads();
    int run = ssum[tid];
    for (int i = s0; i < s1; i++) {
        g_rowptr[m * (NN + 1) + i] = run;
        g_rowcur[m * NN + i] = run;
        run += g_cnt[m * NN + i];
    }
}

__global__ void k_scatter(const int* __restrict__ src, const int* __restrict__ dst) {
    int i = blockIdx.x * blockDim.x + threadIdx.x;
    if (i >= MP * NE) return;
    int m = i / NE;
    int t = dst[i];
    int pos = atomicAdd(&g_rowcur[m * NN + t], 1);
    g_ssrc[(size_t)m * NE + pos] = src[i];
}

// ---------------- per-(dst,path) segment softmax + aggregation ----------------
// One warp per head. alpha computed once per (edge,head), broadcast via shfl.
__global__ __launch_bounds__(256) void k_agg(const float* __restrict__ bias) {
    const int t = blockIdx.x, m = blockIdx.y;
    const int tid = threadIdx.x;
    const int k = tid >> 5, lane = tid & 31;
    const int rp  = g_rowptr[m * (NN + 1) + t];
    const int deg = g_rowptr[m * (NN + 1) + t + 1] - rp;
    const float* el = g_el + (size_t)m * NN * NH;
    const int* ss = g_ssrc + (size_t)m * NE + rp;
    const float erk = g_er[((size_t)m * NN + t) * NH + k];
    const float* fb = g_feat + (size_t)m * NN * DF + k * DOUTD + lane;

    float acc = 0.f;
    if (deg > 0) {
        if (deg <= 32) {
            int sj = 0; float e = -FLT_MAX;
            if (lane < deg) {
                sj = ss[lane];
                float ev = el[sj * NH + k] + erk;
                e = ev > 0.f ? ev : 0.2f * ev;
            }
            float mx = e;
#pragma unroll
            for (int o = 16; o > 0; o >>= 1) mx = fmaxf(mx, __shfl_xor_sync(0xffffffffu, mx, o));
            float ex = (lane < deg) ? expf(e - mx) : 0.f;
            float dn = ex;
#pragma unroll
            for (int o = 16; o > 0; o >>= 1) dn += __shfl_xor_sync(0xffffffffu, dn, o);
            float a = ex * (1.f / (dn + 1e-9f));
            for (int q = 0; q < deg; q++) {
                float aq = __shfl_sync(0xffffffffu, a, q);
                int sq   = __shfl_sync(0xffffffffu, sj, q);
                acc += aq * fb[(size_t)sq * DF];
            }
        } else {
            float mx = -FLT_MAX;
            for (int j = lane; j < deg; j += 32) {
                int s = ss[j];
                float ev = el[s * NH + k] + erk;
                ev = ev > 0.f ? ev : 0.2f * ev;
                mx = fmaxf(mx, ev);
            }
#pragma unroll
            for (int o = 16; o > 0; o >>= 1) mx = fmaxf(mx, __shfl_xor_sync(0xffffffffu, mx, o));
            float dn = 0.f;
            for (int j = lane; j < deg; j += 32) {
                int s = ss[j];
                float ev = el[s * NH + k] + erk;
                ev = ev > 0.f ? ev : 0.2f * ev;
                dn += expf(ev - mx);
            }
#pragma unroll
            for (int o = 16; o > 0; o >>= 1) dn += __shfl_xor_sync(0xffffffffu, dn, o);
            float inv = 1.f / (dn + 1e-9f);
            for (int base = 0; base < deg; base += 32) {
                int jj = base + lane;
                int sj = 0; float a = 0.f;
                if (jj < deg) {
                    sj = ss[jj];
                    float ev = el[sj * NH + k] + erk;
                    ev = ev > 0.f ? ev : 0.2f * ev;
                    a = expf(ev - mx) * inv;
                }
                int cnt = min(32, deg - base);
                for (int q = 0; q < cnt; q++) {
                    float aq = __shfl_sync(0xffffffffu, a, q);
                    int sq   = __shfl_sync(0xffffffffu, sj, q);
                    acc += aq * fb[(size_t)sq * DF];
                }
            }
        }
    }
    acc += bias[m * DF + tid];
    float zv = acc > 0.f ? acc : expm1f(acc);
    g_z[((size_t)m * NN + t) * DF + tid] = zv;
}

// ---------------- GEMM2: fused semantic attention logits, double-buffered ----------------
__global__ __launch_bounds__(256) void k_gemm_sem(const float* __restrict__ W1,
                                                  const float* __restrict__ b1,
                                                  const float* __restrict__ w2) {
    __shared__ float As[2][8][128];
    __shared__ float Bs[2][8][128];
    __shared__ float s_w[MP];
    const int R = MP * NN;
    const int rowBase = blockIdx.x * 128;
    const int tid = threadIdx.x;
    const int tx = tid & 15, ty = tid >> 4;
    const int a_row = tid >> 1;
    const int a_k4  = (tid & 1) * 4;
    int agr = rowBase + a_row; if (agr >= R) agr = R - 1;
    const int b_krow = tid >> 5;
    const int b_col  = (tid & 31) * 4;
    const float* A = g_z;

    float acc[8][8];
#pragma unroll
    for (int i = 0; i < 8; i++)
#pragma unroll
        for (int j = 0; j < 8; j++) acc[i][j] = 0.f;

    {
        float4 av = *(const float4*)&A[(size_t)agr * DF + a_k4];
        float4 bv = *(const float4*)&W1[(size_t)b_krow * HIDN + b_col];
        As[0][a_k4 + 0][a_row] = av.x; As[0][a_k4 + 1][a_row] = av.y;
        As[0][a_k4 + 2][a_row] = av.z; As[0][a_k4 + 3][a_row] = av.w;
        *(float4*)&Bs[0][b_krow][b_col] = bv;
    }
    __syncthreads();

    int cur = 0;
    for (int kt = 0; kt < 256; kt += 8) {
        float4 av2, bv2;
        const bool more = (kt + 8 < 256);
        if (more) {
            av2 = *(const float4*)&A[(size_t)agr * DF + kt + 8 + a_k4];
            bv2 = *(const float4*)&W1[(size_t)(kt + 8 + b_krow) * HIDN + b_col];
        }
#pragma unroll
        for (int kk = 0; kk < 8; kk++) {
            float4 a0 = *(const float4*)&As[cur][kk][ty * 8];
            float4 a1 = *(const float4*)&As[cur][kk][ty * 8 + 4];
            float4 b0 = *(const float4*)&Bs[cur][kk][tx * 8];
            float4 b1v = *(const float4*)&Bs[cur][kk][tx * 8 + 4];
            float ar8[8] = {a0.x, a0.y, a0.z, a0.w, a1.x, a1.y, a1.z, a1.w};
            float br8[8] = {b0.x, b0.y, b0.z, b0.w, b1v.x, b1v.y, b1v.z, b1v.w};
#pragma unroll
            for (int i = 0; i < 8; i++)
#pragma unroll
                for (int j = 0; j < 8; j++) acc[i][j] += ar8[i] * br8[j];
        }
        if (more) {
            int nxt = cur ^ 1;
            As[nxt][a_k4 + 0][a_row] = av2.x; As[nxt][a_k4 + 1][a_row] = av2.y;
            As[nxt][a_k4 + 2][a_row] = av2.z; As[nxt][a_k4 + 3][a_row] = av2.w;
            *(float4*)&Bs[nxt][b_krow][b_col] = bv2;
            __syncthreads();
            cur = nxt;
        }
    }

    if (tid < MP) s_w[tid] = 0.f;
    __syncthreads();

    float rsum[8];
#pragma unroll
    for (int i = 0; i < 8; i++) {
        float s = 0.f;
#pragma unroll
        for (int j = 0; j < 8; j++) {
            int col = tx * 8 + j;
            s += tanhf(acc[i][j] + b1[col]) * w2[col];
        }
#pragma unroll
        for (int o = 1; o < 16; o <<= 1) s += __shfl_xor_sync(0xffffffffu, s, o);
        rsum[i] = s;
    }
    if (tx == 0) {
#pragma unroll
        for (int i = 0; i < 8; i++) {
            int gr = rowBase + ty * 8 + i;
            if (gr < R) atomicAdd(&s_w[gr / NN], rsum[i]);
        }
    }
    __syncthreads();
    if (tid < MP) atomicAdd(&g_w[tid], s_w[tid]);
}

__global__ void k_beta() {
    if (threadIdx.x == 0 && blockIdx.x == 0) {
        float w0 = g_w[0] / (float)NN, w1 = g_w[1] / (float)NN, w2v = g_w[2] / (float)NN;
        float mx = fmaxf(w0, fmaxf(w1, w2v));
        float e0 = expf(w0 - mx), e1 = expf(w1 - mx), e2 = expf(w2v - mx);
        float s = e0 + e1 + e2;
        g_beta[0] = e0 / s; g_beta[1] = e1 / s; g_beta[2] = e2 / s;
    }
}

__global__ void k_final(float* __restrict__ out) {
    int i = blockIdx.x * blockDim.x + threadIdx.x;
    if (i >= NN * DF) return;
    float b0 = g_beta[0], b1 = g_beta[1], b2 = g_beta[2];
    out[i] = b0 * g_z[i] + b1 * g_z[(size_t)NN * DF + i] + b2 * g_z[(size_t)2 * NN * DF + i];
}

extern "C" void kernel_launch(void* const* d_in, const int* in_sizes, int n_in,
                              void* d_out, int out_size) {
    const float* h  = (const float*)d_in[0];
    const float* Wg = (const float*)d_in[1];
    const float* al = (const float*)d_in[2];
    const float* ar = (const float*)d_in[3];
    const float* bg = (const float*)d_in[4];
    const float* W1 = (const float*)d_in[5];
    const float* b1 = (const float*)d_in[6];
    const float* w2 = (const float*)d_in[7];
    const int* src  = (const int*)d_in[8];
    const int* dst  = (const int*)d_in[9];
    float* out = (float*)d_out;

    k_zero<<<(MP * NN + 255) / 256, 256>>>();
    k_gemm_feat<<<dim3((NN + 127) / 128, DF / 128, MP), 256>>>(h, Wg);
    k_eler<<<(MP * NN * NH + 255) / 256, 256>>>(al, ar);
    k_hist<<<(MP * NE + 255) / 256, 256>>>(dst);
    k_scan<<<MP, 1024>>>();
    k_scatter<<<(MP * NE + 255) / 256, 256>>>(src, dst);
    k_agg<<<dim3(NN, MP), 256>>>(bg);
    k_gemm_sem<<<(MP * NN + 127) / 128, 256>>>(W1, b1, w2);
    k_beta<<<1, 1>>>();
    k_final<<<(NN * DF + 255) / 256, 256>>>(out);
}

// round 4
// speedup vs baseline: 1.7750x; 1.2922x over previous
#include <cuda_runtime.h>
#include <math.h>
#include <float.h>

#define NN 50000
#define NE 800000
#define MP 3
#define DF 256
#define NH 8
#define DOUTD 32
#define HIDN 128
#define RTOT (MP * NN)

// ---------------- scratch (static device memory; no allocation) ----------------
__device__ float g_feat[(size_t)MP * NN * DF];
__device__ float g_z[(size_t)MP * NN * DF];
__device__ float g_el[MP * NN * NH];
__device__ float g_er[MP * NN * NH];
__device__ int   g_cnt[MP * NN];
__device__ int   g_rowptr[MP * (NN + 1)];
__device__ int   g_rowcur[MP * NN];
__device__ int   g_ssrc[MP * NE];
__device__ float g_w[MP];
__device__ float g_beta[MP];

__global__ void k_zero() {
    int i = blockIdx.x * blockDim.x + threadIdx.x;
    if (i < MP * NN) g_cnt[i] = 0;
    if (i < MP) g_w[i] = 0.f;
}

// ---------------- tf32 mma helpers ----------------
__device__ __forceinline__ unsigned f2tf(float x) {
    unsigned u; asm("cvt.rna.tf32.f32 %0, %1;" : "=r"(u) : "f"(x)); return u;
}
__device__ __forceinline__ void mma8(float* c, const unsigned* a, unsigned b0, unsigned b1) {
    asm volatile("mma.sync.aligned.m16n8k8.row.col.f32.tf32.tf32.f32 "
                 "{%0,%1,%2,%3}, {%4,%5,%6,%7}, {%8,%9}, {%0,%1,%2,%3};"
                 : "+f"(c[0]), "+f"(c[1]), "+f"(c[2]), "+f"(c[3])
                 : "r"(a[0]), "r"(a[1]), "r"(a[2]), "r"(a[3]), "r"(b0), "r"(b1));
}

// ---------------- GEMM1 (tensor): feat[m] = h @ W_gat[m]  (50000x128 @ 128x256) ----------------
// block tile 128x128, BK=16 double-buffered, 8 warps each 32x64
__global__ __launch_bounds__(256, 2) void k_gemm_feat(const float* __restrict__ A,
                                                      const float* __restrict__ Wg) {
    __shared__ unsigned As[2][128][20];
    __shared__ unsigned Bs[2][16][136];
    const int m = blockIdx.z;
    const float* B = Wg + (size_t)m * 128 * DF;
    float* C = g_feat + (size_t)m * NN * DF;
    const int rowBase = blockIdx.x * 128;
    const int colBase = blockIdx.y * 128;
    const int tid = threadIdx.x;
    const int wid = tid >> 5, lane = tid & 31;
    const int warpM = wid & 3, warpN = wid >> 2;
    const int t4 = lane >> 2, c4 = lane & 3;

    const int ar = tid >> 2, ac = (tid & 3) * 4;       // A loader: 2 passes of 64 rows
    const int bk = tid >> 4, bc = (tid & 15) * 4;      // B loader: 2 passes of 64 cols

    float acc[2][8][4];
#pragma unroll
    for (int i = 0; i < 2; i++)
#pragma unroll
        for (int j = 0; j < 8; j++)
#pragma unroll
            for (int q = 0; q < 4; q++) acc[i][j][q] = 0.f;

    // prologue: chunk 0 -> buf 0
#pragma unroll
    for (int p = 0; p < 2; p++) {
        int r = ar + p * 64;
        int gr = rowBase + r; if (gr >= NN) gr = NN - 1;
        float4 v = *(const float4*)&A[(size_t)gr * 128 + ac];
        unsigned uv[4] = {f2tf(v.x), f2tf(v.y), f2tf(v.z), f2tf(v.w)};
        *(uint4*)&As[0][r][ac] = *(uint4*)uv;
        int c = bc + p * 64;
        float4 bv = *(const float4*)&B[(size_t)bk * DF + colBase + c];
        unsigned bu[4] = {f2tf(bv.x), f2tf(bv.y), f2tf(bv.z), f2tf(bv.w)};
        *(uint4*)&Bs[0][bk][c] = *(uint4*)bu;
    }
    __syncthreads();

    int cur = 0;
    for (int kt = 0; kt < 128; kt += 16) {
        float4 rA[2], rB[2];
        const bool more = (kt + 16 < 128);
        if (more) {
#pragma unroll
            for (int p = 0; p < 2; p++) {
                int r = ar + p * 64;
                int gr = rowBase + r; if (gr >= NN) gr = NN - 1;
                rA[p] = *(const float4*)&A[(size_t)gr * 128 + kt + 16 + ac];
                rB[p] = *(const float4*)&B[(size_t)(kt + 16 + bk) * DF + colBase + bc + p * 64];
            }
        }
#pragma unroll
        for (int ks = 0; ks < 2; ks++) {
            const int k = ks * 8;
            unsigned af[2][4];
#pragma unroll
            for (int mt = 0; mt < 2; mt++) {
                int r = warpM * 32 + mt * 16 + t4;
                af[mt][0] = As[cur][r][k + c4];
                af[mt][1] = As[cur][r + 8][k + c4];
                af[mt][2] = As[cur][r][k + c4 + 4];
                af[mt][3] = As[cur][r + 8][k + c4 + 4];
            }
#pragma unroll
            for (int nt = 0; nt < 8; nt++) {
                int n = warpN * 64 + nt * 8 + t4;
                unsigned b0 = Bs[cur][k + c4][n];
                unsigned b1 = Bs[cur][k + c4 + 4][n];
                mma8(acc[0][nt], af[0], b0, b1);
                mma8(acc[1][nt], af[1], b0, b1);
            }
        }
        if (more) {
            int nxt = cur ^ 1;
#pragma unroll
            for (int p = 0; p < 2; p++) {
                int r = ar + p * 64;
                unsigned uv[4] = {f2tf(rA[p].x), f2tf(rA[p].y), f2tf(rA[p].z), f2tf(rA[p].w)};
                *(uint4*)&As[nxt][r][ac] = *(uint4*)uv;
                unsigned bu[4] = {f2tf(rB[p].x), f2tf(rB[p].y), f2tf(rB[p].z), f2tf(rB[p].w)};
                *(uint4*)&Bs[nxt][bk][bc + p * 64] = *(uint4*)bu;
            }
            __syncthreads();
            cur = nxt;
        }
    }

    // epilogue
#pragma unroll
    for (int mt = 0; mt < 2; mt++) {
        int r0 = rowBase + warpM * 32 + mt * 16 + t4;
        int r1 = r0 + 8;
#pragma unroll
        for (int nt = 0; nt < 8; nt++) {
            int cg = colBase + warpN * 64 + nt * 8 + c4 * 2;
            if (r0 < NN) { float2 v = {acc[mt][nt][0], acc[mt][nt][1]}; *(float2*)&C[(size_t)r0 * DF + cg] = v; }
            if (r1 < NN) { float2 v = {acc[mt][nt][2], acc[mt][nt][3]}; *(float2*)&C[(size_t)r1 * DF + cg] = v; }
        }
    }
}

// ---------------- el/er ----------------
__global__ void k_eler(const float* __restrict__ al, const float* __restrict__ ar) {
    int idx = blockIdx.x * blockDim.x + threadIdx.x;
    if (idx >= MP * NN * NH) return;
    int m = idx / (NN * NH);
    int r = idx % (NN * NH);
    int n = r / NH, k = r % NH;
    const float* f   = g_feat + ((size_t)m * NN + n) * DF + k * DOUTD;
    const float* alp = al + (m * NH + k) * DOUTD;
    const float* arp = ar + (m * NH + k) * DOUTD;
    float sl = 0.f, sr = 0.f;
#pragma unroll
    for (int j = 0; j < DOUTD; j += 4) {
        float4 fv = *(const float4*)&f[j];
        float4 lv = *(const float4*)&alp[j];
        float4 rv = *(const float4*)&arp[j];
        sl += fv.x * lv.x + fv.y * lv.y + fv.z * lv.z + fv.w * lv.w;
        sr += fv.x * rv.x + fv.y * rv.y + fv.z * rv.z + fv.w * rv.w;
    }
    g_el[idx] = sl;
    g_er[idx] = sr;
}

// ---------------- CSR build ----------------
__global__ void k_hist(const int* __restrict__ dst) {
    int i = blockIdx.x * blockDim.x + threadIdx.x;
    if (i >= MP * NE) return;
    int m = i / NE;
    atomicAdd(&g_cnt[m * NN + dst[i]], 1);
}

__global__ void k_scan() {
    const int m = blockIdx.x;
    __shared__ int ssum[1024];
    const int tid = threadIdx.x;
    const int CH = (NN + 1023) / 1024;
    int s0 = tid * CH, s1 = min(s0 + CH, NN);
    int acc = 0;
    for (int i = s0; i < s1; i++) acc += g_cnt[m * NN + i];
    ssum[tid] = acc;
    __syncthreads();
    if (tid == 0) {
        int run = 0;
        for (int j = 0; j < 1024; j++) { int v = ssum[j]; ssum[j] = run; run += v; }
        g_rowptr[m * (NN + 1) + NN] = run;
    }
    __syncthreads();
    int run = ssum[tid];
    for (int i = s0; i < s1; i++) {
        g_rowptr[m * (NN + 1) + i] = run;
        g_rowcur[m * NN + i] = run;
        run += g_cnt[m * NN + i];
    }
}

__global__ void k_scatter(const int* __restrict__ src, const int* __restrict__ dst) {
    int i = blockIdx.x * blockDim.x + threadIdx.x;
    if (i >= MP * NE) return;
    int m = i / NE;
    int t = dst[i];
    int pos = atomicAdd(&g_rowcur[m * NN + t], 1);
    g_ssrc[(size_t)m * NE + pos] = src[i];
}

// ---------------- segment softmax + aggregation ----------------
__global__ __launch_bounds__(256) void k_agg(const float* __restrict__ bias) {
    const int t = blockIdx.x, m = blockIdx.y;
    const int tid = threadIdx.x;
    const int k = tid >> 5, lane = tid & 31;
    const int rp  = g_rowptr[m * (NN + 1) + t];
    const int deg = g_rowptr[m * (NN + 1) + t + 1] - rp;
    const float* el = g_el + (size_t)m * NN * NH;
    const int* ss = g_ssrc + (size_t)m * NE + rp;
    const float erk = g_er[((size_t)m * NN + t) * NH + k];
    const float* fb = g_feat + (size_t)m * NN * DF + k * DOUTD + lane;

    float acc = 0.f;
    if (deg > 0) {
        if (deg <= 32) {
            int sj = 0; float e = -FLT_MAX;
            if (lane < deg) {
                sj = ss[lane];
                float ev = el[sj * NH + k] + erk;
                e = ev > 0.f ? ev : 0.2f * ev;
            }
            float mx = e;
#pragma unroll
            for (int o = 16; o > 0; o >>= 1) mx = fmaxf(mx, __shfl_xor_sync(0xffffffffu, mx, o));
            float ex = (lane < deg) ? expf(e - mx) : 0.f;
            float dn = ex;
#pragma unroll
            for (int o = 16; o > 0; o >>= 1) dn += __shfl_xor_sync(0xffffffffu, dn, o);
            float a = ex * (1.f / (dn + 1e-9f));
            for (int q = 0; q < deg; q++) {
                float aq = __shfl_sync(0xffffffffu, a, q);
                int sq   = __shfl_sync(0xffffffffu, sj, q);
                acc += aq * fb[(size_t)sq * DF];
            }
        } else {
            float mx = -FLT_MAX;
            for (int j = lane; j < deg; j += 32) {
                int s = ss[j];
                float ev = el[s * NH + k] + erk;
                ev = ev > 0.f ? ev : 0.2f * ev;
                mx = fmaxf(mx, ev);
            }
#pragma unroll
            for (int o = 16; o > 0; o >>= 1) mx = fmaxf(mx, __shfl_xor_sync(0xffffffffu, mx, o));
            float dn = 0.f;
            for (int j = lane; j < deg; j += 32) {
                int s = ss[j];
                float ev = el[s * NH + k] + erk;
                ev = ev > 0.f ? ev : 0.2f * ev;
                dn += expf(ev - mx);
            }
#pragma unroll
            for (int o = 16; o > 0; o >>= 1) dn += __shfl_xor_sync(0xffffffffu, dn, o);
            float inv = 1.f / (dn + 1e-9f);
            for (int base = 0; base < deg; base += 32) {
                int jj = base + lane;
                int sj = 0; float a = 0.f;
                if (jj < deg) {
                    sj = ss[jj];
                    float ev = el[sj * NH + k] + erk;
                    ev = ev > 0.f ? ev : 0.2f * ev;
                    a = expf(ev - mx) * inv;
                }
                int cnt = min(32, deg - base);
                for (int q = 0; q < cnt; q++) {
                    float aq = __shfl_sync(0xffffffffu, a, q);
                    int sq   = __shfl_sync(0xffffffffu, sj, q);
                    acc += aq * fb[(size_t)sq * DF];
                }
            }
        }
    }
    acc += bias[m * DF + tid];
    float zv = acc > 0.f ? acc : expm1f(acc);
    g_z[((size_t)m * NN + t) * DF + tid] = zv;
}

// ---------------- GEMM2 (tensor): fused semantic attention logits ----------------
// z (150000x256) @ W1 (256x128), epilogue: w[m] += sum_row( tanh(row + b1) . w2 )
__global__ __launch_bounds__(256, 2) void k_gemm_sem(const float* __restrict__ W1,
                                                     const float* __restrict__ b1,
                                                     const float* __restrict__ w2) {
    __shared__ unsigned As[2][128][20];
    __shared__ unsigned Bs[2][16][136];
    __shared__ float s_w[MP];
    const float* A = g_z;
    const int rowBase = blockIdx.x * 128;
    const int tid = threadIdx.x;
    const int wid = tid >> 5, lane = tid & 31;
    const int warpM = wid & 3, warpN = wid >> 2;
    const int t4 = lane >> 2, c4 = lane & 3;

    const int ar = tid >> 2, ac = (tid & 3) * 4;
    const int bk = tid >> 4, bc = (tid & 15) * 4;

    float acc[2][8][4];
#pragma unroll
    for (int i = 0; i < 2; i++)
#pragma unroll
        for (int j = 0; j < 8; j++)
#pragma unroll
            for (int q = 0; q < 4; q++) acc[i][j][q] = 0.f;

    if (tid < MP) s_w[tid] = 0.f;

#pragma unroll
    for (int p = 0; p < 2; p++) {
        int r = ar + p * 64;
        int gr = rowBase + r; if (gr >= RTOT) gr = RTOT - 1;
        float4 v = *(const float4*)&A[(size_t)gr * DF + ac];
        unsigned uv[4] = {f2tf(v.x), f2tf(v.y), f2tf(v.z), f2tf(v.w)};
        *(uint4*)&As[0][r][ac] = *(uint4*)uv;
        int c = bc + p * 64;
        float4 bv = *(const float4*)&W1[(size_t)bk * HIDN + c];
        unsigned bu[4] = {f2tf(bv.x), f2tf(bv.y), f2tf(bv.z), f2tf(bv.w)};
        *(uint4*)&Bs[0][bk][c] = *(uint4*)bu;
    }
    __syncthreads();

    int cur = 0;
    for (int kt = 0; kt < 256; kt += 16) {
        float4 rA[2], rB[2];
        const bool more = (kt + 16 < 256);
        if (more) {
#pragma unroll
            for (int p = 0; p < 2; p++) {
                int r = ar + p * 64;
                int gr = rowBase + r; if (gr >= RTOT) gr = RTOT - 1;
                rA[p] = *(const float4*)&A[(size_t)gr * DF + kt + 16 + ac];
                rB[p] = *(const float4*)&W1[(size_t)(kt + 16 + bk) * HIDN + bc + p * 64];
            }
        }
#pragma unroll
        for (int ks = 0; ks < 2; ks++) {
            const int k = ks * 8;
            unsigned af[2][4];
#pragma unroll
            for (int mt = 0; mt < 2; mt++) {
                int r = warpM * 32 + mt * 16 + t4;
                af[mt][0] = As[cur][r][k + c4];
                af[mt][1] = As[cur][r + 8][k + c4];
                af[mt][2] = As[cur][r][k + c4 + 4];
                af[mt][3] = As[cur][r + 8][k + c4 + 4];
            }
#pragma unroll
            for (int nt = 0; nt < 8; nt++) {
                int n = warpN * 64 + nt * 8 + t4;
                unsigned b0 = Bs[cur][k + c4][n];
                unsigned b1v = Bs[cur][k + c4 + 4][n];
                mma8(acc[0][nt], af[0], b0, b1v);
                mma8(acc[1][nt], af[1], b0, b1v);
            }
        }
        if (more) {
            int nxt = cur ^ 1;
#pragma unroll
            for (int p = 0; p < 2; p++) {
                int r = ar + p * 64;
                unsigned uv[4] = {f2tf(rA[p].x), f2tf(rA[p].y), f2tf(rA[p].z), f2tf(rA[p].w)};
                *(uint4*)&As[nxt][r][ac] = *(uint4*)uv;
                unsigned bu[4] = {f2tf(rB[p].x), f2tf(rB[p].y), f2tf(rB[p].z), f2tf(rB[p].w)};
                *(uint4*)&Bs[nxt][bk][bc + p * 64] = *(uint4*)bu;
            }
            __syncthreads();
            cur = nxt;
        }
    }

    // fused epilogue: tanh + dot(w2) + row-reduce + per-path accumulate
#pragma unroll
    for (int mt = 0; mt < 2; mt++) {
        float p0 = 0.f, p1 = 0.f;
#pragma unroll
        for (int nt = 0; nt < 8; nt++) {
            int cg = warpN * 64 + nt * 8 + c4 * 2;
            float b1a = b1[cg], b1b = b1[cg + 1];
            float w2a = w2[cg], w2b = w2[cg + 1];
            p0 += tanhf(acc[mt][nt][0] + b1a) * w2a + tanhf(acc[mt][nt][1] + b1b) * w2b;
            p1 += tanhf(acc[mt][nt][2] + b1a) * w2a + tanhf(acc[mt][nt][3] + b1b) * w2b;
        }
        p0 += __shfl_xor_sync(0xffffffffu, p0, 1);
        p0 += __shfl_xor_sync(0xffffffffu, p0, 2);
        p1 += __shfl_xor_sync(0xffffffffu, p1, 1);
        p1 += __shfl_xor_sync(0xffffffffu, p1, 2);
        if (c4 == 0) {
            int r0 = rowBase + warpM * 32 + mt * 16 + t4;
            int r1 = r0 + 8;
            if (r0 < RTOT) atomicAdd(&s_w[r0 / NN], p0);
            if (r1 < RTOT) atomicAdd(&s_w[r1 / NN], p1);
        }
    }
    __syncthreads();
    if (tid < MP) atomicAdd(&g_w[tid], s_w[tid]);
}

__global__ void k_beta() {
    if (threadIdx.x == 0 && blockIdx.x == 0) {
        float w0 = g_w[0] / (float)NN, w1 = g_w[1] / (float)NN, w2v = g_w[2] / (float)NN;
        float mx = fmaxf(w0, fmaxf(w1, w2v));
        float e0 = expf(w0 - mx), e1 = expf(w1 - mx), e2 = expf(w2v - mx);
        float s = e0 + e1 + e2;
        g_beta[0] = e0 / s; g_beta[1] = e1 / s; g_beta[2] = e2 / s;
    }
}

__global__ void k_final(float* __restrict__ out) {
    int i = blockIdx.x * blockDim.x + threadIdx.x;
    if (i >= NN * DF) return;
    float b0 = g_beta[0], b1 = g_beta[1], b2 = g_beta[2];
    out[i] = b0 * g_z[i] + b1 * g_z[(size_t)NN * DF + i] + b2 * g_z[(size_t)2 * NN * DF + i];
}

extern "C" void kernel_launch(void* const* d_in, const int* in_sizes, int n_in,
                              void* d_out, int out_size) {
    const float* h  = (const float*)d_in[0];
    const float* Wg = (const float*)d_in[1];
    const float* al = (const float*)d_in[2];
    const float* ar = (const float*)d_in[3];
    const float* bg = (const float*)d_in[4];
    const float* W1 = (const float*)d_in[5];
    const float* b1 = (const float*)d_in[6];
    const float* w2 = (const float*)d_in[7];
    const int* src  = (const int*)d_in[8];
    const int* dst  = (const int*)d_in[9];
    float* out = (float*)d_out;

    k_zero<<<(MP * NN + 255) / 256, 256>>>();
    k_gemm_feat<<<dim3((NN + 127) / 128, DF / 128, MP), 256>>>(h, Wg);
    k_eler<<<(MP * NN * NH + 255) / 256, 256>>>(al, ar);
    k_hist<<<(MP * NE + 255) / 256, 256>>>(dst);
    k_scan<<<MP, 1024>>>();
    k_scatter<<<(MP * NE + 255) / 256, 256>>>(src, dst);
    k_agg<<<dim3(NN, MP), 256>>>(bg);
    k_gemm_sem<<<(RTOT + 127) / 128, 256>>>(W1, b1, w2);
    k_beta<<<1, 1>>>();
    k_final<<<(NN * DF + 255) / 256, 256>>>(out);
}

// round 5
// speedup vs baseline: 1.9652x; 1.1071x over previous
#include <cuda_runtime.h>
#include <math.h>
#include <float.h>

#define NN 50000
#define NE 800000
#define MP 3
#define DF 256
#define NH 8
#define DOUTD 32
#define HIDN 128
#define RTOT (MP * NN)

// ---------------- scratch (static device memory; no allocation) ----------------
__device__ float g_feat[(size_t)MP * NN * DF];
__device__ float g_z[(size_t)MP * NN * DF];
__device__ float g_el[MP * NN * NH];
__device__ float g_er[MP * NN * NH];
__device__ int   g_cnt[MP * NN];
__device__ int   g_rowptr[MP * (NN + 1)];
__device__ int   g_rowcur[MP * NN];
__device__ int   g_ssrc[MP * NE];
__device__ float g_w[MP];
__device__ float g_beta[MP];

__global__ void k_zero() {
    int i = blockIdx.x * blockDim.x + threadIdx.x;
    if (i < MP * NN) g_cnt[i] = 0;
    if (i < MP) g_w[i] = 0.f;
}

// ---------------- tf32 mma helpers ----------------
__device__ __forceinline__ unsigned f2tf(float x) {
    unsigned u; asm("cvt.rna.tf32.f32 %0, %1;" : "=r"(u) : "f"(x)); return u;
}
__device__ __forceinline__ void mma8(float* c, const unsigned* a, unsigned b0, unsigned b1) {
    asm volatile("mma.sync.aligned.m16n8k8.row.col.f32.tf32.tf32.f32 "
                 "{%0,%1,%2,%3}, {%4,%5,%6,%7}, {%8,%9}, {%0,%1,%2,%3};"
                 : "+f"(c[0]), "+f"(c[1]), "+f"(c[2]), "+f"(c[3])
                 : "r"(a[0]), "r"(a[1]), "r"(a[2]), "r"(a[3]), "r"(b0), "r"(b1));
}

// ---------------- GEMM1 (tensor): feat[m] = h @ W_gat[m] + fused el/er epilogue ----------------
// block tile 128x128, BK=16 double-buffered, 8 warps each 32x64
__global__ __launch_bounds__(256, 2) void k_gemm_feat(const float* __restrict__ A,
                                                      const float* __restrict__ Wg,
                                                      const float* __restrict__ attl,
                                                      const float* __restrict__ attr) {
    __shared__ unsigned As[2][128][20];
    __shared__ unsigned Bs[2][16][136];
    const int m = blockIdx.z;
    const float* B = Wg + (size_t)m * 128 * DF;
    float* C = g_feat + (size_t)m * NN * DF;
    const int rowBase = blockIdx.x * 128;
    const int colBase = blockIdx.y * 128;
    const int tid = threadIdx.x;
    const int wid = tid >> 5, lane = tid & 31;
    const int warpM = wid & 3, warpN = wid >> 2;
    const int t4 = lane >> 2, c4 = lane & 3;

    const int ar = tid >> 2, ac = (tid & 3) * 4;
    const int bk = tid >> 4, bc = (tid & 15) * 4;

    float acc[2][8][4];
#pragma unroll
    for (int i = 0; i < 2; i++)
#pragma unroll
        for (int j = 0; j < 8; j++)
#pragma unroll
            for (int q = 0; q < 4; q++) acc[i][j][q] = 0.f;

#pragma unroll
    for (int p = 0; p < 2; p++) {
        int r = ar + p * 64;
        int gr = rowBase + r; if (gr >= NN) gr = NN - 1;
        float4 v = *(const float4*)&A[(size_t)gr * 128 + ac];
        unsigned uv[4] = {f2tf(v.x), f2tf(v.y), f2tf(v.z), f2tf(v.w)};
        *(uint4*)&As[0][r][ac] = *(uint4*)uv;
        int c = bc + p * 64;
        float4 bv = *(const float4*)&B[(size_t)bk * DF + colBase + c];
        unsigned bu[4] = {f2tf(bv.x), f2tf(bv.y), f2tf(bv.z), f2tf(bv.w)};
        *(uint4*)&Bs[0][bk][c] = *(uint4*)bu;
    }
    __syncthreads();

    int cur = 0;
    for (int kt = 0; kt < 128; kt += 16) {
        float4 rA[2], rB[2];
        const bool more = (kt + 16 < 128);
        if (more) {
#pragma unroll
            for (int p = 0; p < 2; p++) {
                int r = ar + p * 64;
                int gr = rowBase + r; if (gr >= NN) gr = NN - 1;
                rA[p] = *(const float4*)&A[(size_t)gr * 128 + kt + 16 + ac];
                rB[p] = *(const float4*)&B[(size_t)(kt + 16 + bk) * DF + colBase + bc + p * 64];
            }
        }
#pragma unroll
        for (int ks = 0; ks < 2; ks++) {
            const int k = ks * 8;
            unsigned af[2][4];
#pragma unroll
            for (int mt = 0; mt < 2; mt++) {
                int r = warpM * 32 + mt * 16 + t4;
                af[mt][0] = As[cur][r][k + c4];
                af[mt][1] = As[cur][r + 8][k + c4];
                af[mt][2] = As[cur][r][k + c4 + 4];
                af[mt][3] = As[cur][r + 8][k + c4 + 4];
            }
#pragma unroll
            for (int nt = 0; nt < 8; nt++) {
                int n = warpN * 64 + nt * 8 + t4;
                unsigned b0 = Bs[cur][k + c4][n];
                unsigned b1 = Bs[cur][k + c4 + 4][n];
                mma8(acc[0][nt], af[0], b0, b1);
                mma8(acc[1][nt], af[1], b0, b1);
            }
        }
        if (more) {
            int nxt = cur ^ 1;
#pragma unroll
            for (int p = 0; p < 2; p++) {
                int r = ar + p * 64;
                unsigned uv[4] = {f2tf(rA[p].x), f2tf(rA[p].y), f2tf(rA[p].z), f2tf(rA[p].w)};
                *(uint4*)&As[nxt][r][ac] = *(uint4*)uv;
                unsigned bu[4] = {f2tf(rB[p].x), f2tf(rB[p].y), f2tf(rB[p].z), f2tf(rB[p].w)};
                *(uint4*)&Bs[nxt][bk][bc + p * 64] = *(uint4*)bu;
            }
            __syncthreads();
            cur = nxt;
        }
    }

    // epilogue: store C
#pragma unroll
    for (int mt = 0; mt < 2; mt++) {
        int r0 = rowBase + warpM * 32 + mt * 16 + t4;
        int r1 = r0 + 8;
#pragma unroll
        for (int nt = 0; nt < 8; nt++) {
            int cg = colBase + warpN * 64 + nt * 8 + c4 * 2;
            if (r0 < NN) { float2 v = {acc[mt][nt][0], acc[mt][nt][1]}; *(float2*)&C[(size_t)r0 * DF + cg] = v; }
            if (r1 < NN) { float2 v = {acc[mt][nt][2], acc[mt][nt][3]}; *(float2*)&C[(size_t)r1 * DF + cg] = v; }
        }
    }

    // fused el/er: each warp's 64-col span = 2 complete heads
    const float* alm = attl + (size_t)m * NH * DOUTD;
    const float* arm = attr + (size_t)m * NH * DOUTD;
#pragma unroll
    for (int half = 0; half < 2; half++) {
        const int head = (colBase + warpN * 64) / 32 + half;
        const float* av = alm + head * DOUTD;
        const float* rv = arm + head * DOUTD;
#pragma unroll
        for (int mt = 0; mt < 2; mt++) {
            float el0 = 0.f, el1 = 0.f, er0 = 0.f, er1 = 0.f;
#pragma unroll
            for (int ntl = 0; ntl < 4; ntl++) {
                int nt = half * 4 + ntl;
                int d = ntl * 8 + c4 * 2;
                float a0 = av[d], a1 = av[d + 1];
                float q0 = rv[d], q1 = rv[d + 1];
                el0 += acc[mt][nt][0] * a0 + acc[mt][nt][1] * a1;
                el1 += acc[mt][nt][2] * a0 + acc[mt][nt][3] * a1;
                er0 += acc[mt][nt][0] * q0 + acc[mt][nt][1] * q1;
                er1 += acc[mt][nt][2] * q0 + acc[mt][nt][3] * q1;
            }
            el0 += __shfl_xor_sync(0xffffffffu, el0, 1); el0 += __shfl_xor_sync(0xffffffffu, el0, 2);
            el1 += __shfl_xor_sync(0xffffffffu, el1, 1); el1 += __shfl_xor_sync(0xffffffffu, el1, 2);
            er0 += __shfl_xor_sync(0xffffffffu, er0, 1); er0 += __shfl_xor_sync(0xffffffffu, er0, 2);
            er1 += __shfl_xor_sync(0xffffffffu, er1, 1); er1 += __shfl_xor_sync(0xffffffffu, er1, 2);
            if (c4 == 0) {
                int r0 = rowBase + warpM * 32 + mt * 16 + t4;
                int r1 = r0 + 8;
                if (r0 < NN) {
                    g_el[((size_t)m * NN + r0) * NH + head] = el0;
                    g_er[((size_t)m * NN + r0) * NH + head] = er0;
                }
                if (r1 < NN) {
                    g_el[((size_t)m * NN + r1) * NH + head] = el1;
                    g_er[((size_t)m * NN + r1) * NH + head] = er1;
                }
            }
        }
    }
}

// ---------------- CSR build ----------------
__global__ void k_hist(const int* __restrict__ dst) {
    int i = blockIdx.x * blockDim.x + threadIdx.x;
    if (i >= MP * NE) return;
    int m = i / NE;
    atomicAdd(&g_cnt[m * NN + dst[i]], 1);
}

__global__ void k_scan() {
    const int m = blockIdx.x;
    __shared__ int ssum[1024];
    const int tid = threadIdx.x;
    const int CH = (NN + 1023) / 1024;
    int s0 = tid * CH, s1 = min(s0 + CH, NN);
    int acc = 0;
    for (int i = s0; i < s1; i++) acc += g_cnt[m * NN + i];
    ssum[tid] = acc;
    __syncthreads();
    if (tid == 0) {
        int run = 0;
        for (int j = 0; j < 1024; j++) { int v = ssum[j]; ssum[j] = run; run += v; }
        g_rowptr[m * (NN + 1) + NN] = run;
    }
    __syncthreads();
    int run = ssum[tid];
    for (int i = s0; i < s1; i++) {
        g_rowptr[m * (NN + 1) + i] = run;
        g_rowcur[m * NN + i] = run;
        run += g_cnt[m * NN + i];
    }
}

__global__ void k_scatter(const int* __restrict__ src, const int* __restrict__ dst) {
    int i = blockIdx.x * blockDim.x + threadIdx.x;
    if (i >= MP * NE) return;
    int m = i / NE;
    int t = dst[i];
    int pos = atomicAdd(&g_rowcur[m * NN + t], 1);
    g_ssrc[(size_t)m * NE + pos] = src[i];
}

// ---------------- segment softmax + aggregation ----------------
__global__ __launch_bounds__(256) void k_agg(const float* __restrict__ bias) {
    const int t = blockIdx.x, m = blockIdx.y;
    const int tid = threadIdx.x;
    const int k = tid >> 5, lane = tid & 31;
    const int rp  = g_rowptr[m * (NN + 1) + t];
    const int deg = g_rowptr[m * (NN + 1) + t + 1] - rp;
    const float* el = g_el + (size_t)m * NN * NH;
    const int* ss = g_ssrc + (size_t)m * NE + rp;
    const float erk = g_er[((size_t)m * NN + t) * NH + k];
    const float* fb = g_feat + (size_t)m * NN * DF + k * DOUTD + lane;

    float acc = 0.f;
    if (deg > 0) {
        if (deg <= 32) {
            int sj = 0; float e = -FLT_MAX;
            if (lane < deg) {
                sj = ss[lane];
                float ev = el[sj * NH + k] + erk;
                e = ev > 0.f ? ev : 0.2f * ev;
            }
            float mx = e;
#pragma unroll
            for (int o = 16; o > 0; o >>= 1) mx = fmaxf(mx, __shfl_xor_sync(0xffffffffu, mx, o));
            float ex = (lane < deg) ? expf(e - mx) : 0.f;
            float dn = ex;
#pragma unroll
            for (int o = 16; o > 0; o >>= 1) dn += __shfl_xor_sync(0xffffffffu, dn, o);
            float a = ex * (1.f / (dn + 1e-9f));
            for (int q = 0; q < deg; q++) {
                float aq = __shfl_sync(0xffffffffu, a, q);
                int sq   = __shfl_sync(0xffffffffu, sj, q);
                acc += aq * fb[(size_t)sq * DF];
            }
        } else {
            float mx = -FLT_MAX;
            for (int j = lane; j < deg; j += 32) {
                int s = ss[j];
                float ev = el[s * NH + k] + erk;
                ev = ev > 0.f ? ev : 0.2f * ev;
                mx = fmaxf(mx, ev);
            }
#pragma unroll
            for (int o = 16; o > 0; o >>= 1) mx = fmaxf(mx, __shfl_xor_sync(0xffffffffu, mx, o));
            float dn = 0.f;
            for (int j = lane; j < deg; j += 32) {
                int s = ss[j];
                float ev = el[s * NH + k] + erk;
                ev = ev > 0.f ? ev : 0.2f * ev;
                dn += expf(ev - mx);
            }
#pragma unroll
            for (int o = 16; o > 0; o >>= 1) dn += __shfl_xor_sync(0xffffffffu, dn, o);
            float inv = 1.f / (dn + 1e-9f);
            for (int base = 0; base < deg; base += 32) {
                int jj = base + lane;
                int sj = 0; float a = 0.f;
                if (jj < deg) {
                    sj = ss[jj];
                    float ev = el[sj * NH + k] + erk;
                    ev = ev > 0.f ? ev : 0.2f * ev;
                    a = expf(ev - mx) * inv;
                }
                int cnt = min(32, deg - base);
                for (int q = 0; q < cnt; q++) {
                    float aq = __shfl_sync(0xffffffffu, a, q);
                    int sq   = __shfl_sync(0xffffffffu, sj, q);
                    acc += aq * fb[(size_t)sq * DF];
                }
            }
        }
    }
    acc += bias[m * DF + tid];
    float zv = acc > 0.f ? acc : expm1f(acc);
    g_z[((size_t)m * NN + t) * DF + tid] = zv;
}

// ---------------- GEMM2 (tensor): fused semantic attention logits ----------------
__global__ __launch_bounds__(256, 2) void k_gemm_sem(const float* __restrict__ W1,
                                                     const float* __restrict__ b1,
                                                     const float* __restrict__ w2) {
    __shared__ unsigned As[2][128][20];
    __shared__ unsigned Bs[2][16][136];
    __shared__ float s_w[MP];
    const float* A = g_z;
    const int rowBase = blockIdx.x * 128;
    const int tid = threadIdx.x;
    const int wid = tid >> 5, lane = tid & 31;
    const int warpM = wid & 3, warpN = wid >> 2;
    const int t4 = lane >> 2, c4 = lane & 3;

    const int ar = tid >> 2, ac = (tid & 3) * 4;
    const int bk = tid >> 4, bc = (tid & 15) * 4;

    float acc[2][8][4];
#pragma unroll
    for (int i = 0; i < 2; i++)
#pragma unroll
        for (int j = 0; j < 8; j++)
#pragma unroll
            for (int q = 0; q < 4; q++) acc[i][j][q] = 0.f;

    if (tid < MP) s_w[tid] = 0.f;

#pragma unroll
    for (int p = 0; p < 2; p++) {
        int r = ar + p * 64;
        int gr = rowBase + r; if (gr >= RTOT) gr = RTOT - 1;
        float4 v = *(const float4*)&A[(size_t)gr * DF + ac];
        unsigned uv[4] = {f2tf(v.x), f2tf(v.y), f2tf(v.z), f2tf(v.w)};
        *(uint4*)&As[0][r][ac] = *(uint4*)uv;
        int c = bc + p * 64;
        float4 bv = *(const float4*)&W1[(size_t)bk * HIDN + c];
        unsigned bu[4] = {f2tf(bv.x), f2tf(bv.y), f2tf(bv.z), f2tf(bv.w)};
        *(uint4*)&Bs[0][bk][c] = *(uint4*)bu;
    }
    __syncthreads();

    int cur = 0;
    for (int kt = 0; kt < 256; kt += 16) {
        float4 rA[2], rB[2];
        const bool more = (kt + 16 < 256);
        if (more) {
#pragma unroll
            for (int p = 0; p < 2; p++) {
                int r = ar + p * 64;
                int gr = rowBase + r; if (gr >= RTOT) gr = RTOT - 1;
                rA[p] = *(const float4*)&A[(size_t)gr * DF + kt + 16 + ac];
                rB[p] = *(const float4*)&W1[(size_t)(kt + 16 + bk) * HIDN + bc + p * 64];
            }
        }
#pragma unroll
        for (int ks = 0; ks < 2; ks++) {
            const int k = ks * 8;
            unsigned af[2][4];
#pragma unroll
            for (int mt = 0; mt < 2; mt++) {
                int r = warpM * 32 + mt * 16 + t4;
                af[mt][0] = As[cur][r][k + c4];
                af[mt][1] = As[cur][r + 8][k + c4];
                af[mt][2] = As[cur][r][k + c4 + 4];
                af[mt][3] = As[cur][r + 8][k + c4 + 4];
            }
#pragma unroll
            for (int nt = 0; nt < 8; nt++) {
                int n = warpN * 64 + nt * 8 + t4;
                unsigned b0 = Bs[cur][k + c4][n];
                unsigned b1v = Bs[cur][k + c4 + 4][n];
                mma8(acc[0][nt], af[0], b0, b1v);
                mma8(acc[1][nt], af[1], b0, b1v);
            }
        }
        if (more) {
            int nxt = cur ^ 1;
#pragma unroll
            for (int p = 0; p < 2; p++) {
                int r = ar + p * 64;
                unsigned uv[4] = {f2tf(rA[p].x), f2tf(rA[p].y), f2tf(rA[p].z), f2tf(rA[p].w)};
                *(uint4*)&As[nxt][r][ac] = *(uint4*)uv;
                unsigned bu[4] = {f2tf(rB[p].x), f2tf(rB[p].y), f2tf(rB[p].z), f2tf(rB[p].w)};
                *(uint4*)&Bs[nxt][bk][bc + p * 64] = *(uint4*)bu;
            }
            __syncthreads();
            cur = nxt;
        }
    }

    // fused epilogue: tanh + dot(w2) + row-reduce + per-path accumulate
#pragma unroll
    for (int mt = 0; mt < 2; mt++) {
        float p0 = 0.f, p1 = 0.f;
#pragma unroll
        for (int nt = 0; nt < 8; nt++) {
            int cg = warpN * 64 + nt * 8 + c4 * 2;
            float b1a = b1[cg], b1b = b1[cg + 1];
            float w2a = w2[cg], w2b = w2[cg + 1];
            p0 += tanhf(acc[mt][nt][0] + b1a) * w2a + tanhf(acc[mt][nt][1] + b1b) * w2b;
            p1 += tanhf(acc[mt][nt][2] + b1a) * w2a + tanhf(acc[mt][nt][3] + b1b) * w2b;
        }
        p0 += __shfl_xor_sync(0xffffffffu, p0, 1);
        p0 += __shfl_xor_sync(0xffffffffu, p0, 2);
        p1 += __shfl_xor_sync(0xffffffffu, p1, 1);
        p1 += __shfl_xor_sync(0xffffffffu, p1, 2);
        if (c4 == 0) {
            int r0 = rowBase + warpM * 32 + mt * 16 + t4;
            int r1 = r0 + 8;
            if (r0 < RTOT) atomicAdd(&s_w[r0 / NN], p0);
            if (r1 < RTOT) atomicAdd(&s_w[r1 / NN], p1);
        }
    }
    __syncthreads();
    if (tid < MP) atomicAdd(&g_w[tid], s_w[tid]);
}

__global__ void k_beta() {
    if (threadIdx.x == 0 && blockIdx.x == 0) {
        float w0 = g_w[0] / (float)NN, w1 = g_w[1] / (float)NN, w2v = g_w[2] / (float)NN;
        float mx = fmaxf(w0, fmaxf(w1, w2v));
        float e0 = expf(w0 - mx), e1 = expf(w1 - mx), e2 = expf(w2v - mx);
        float s = e0 + e1 + e2;
        g_beta[0] = e0 / s; g_beta[1] = e1 / s; g_beta[2] = e2 / s;
    }
}

__global__ void k_final(float* __restrict__ out) {
    int i = blockIdx.x * blockDim.x + threadIdx.x;
    if (i >= NN * DF) return;
    float b0 = g_beta[0], b1 = g_beta[1], b2 = g_beta[2];
    out[i] = b0 * g_z[i] + b1 * g_z[(size_t)NN * DF + i] + b2 * g_z[(size_t)2 * NN * DF + i];
}

extern "C" void kernel_launch(void* const* d_in, const int* in_sizes, int n_in,
                              void* d_out, int out_size) {
    const float* h  = (const float*)d_in[0];
    const float* Wg = (const float*)d_in[1];
    const float* al = (const float*)d_in[2];
    const float* ar = (const float*)d_in[3];
    const float* bg = (const float*)d_in[4];
    const float* W1 = (const float*)d_in[5];
    const float* b1 = (const float*)d_in[6];
    const float* w2 = (const float*)d_in[7];
    const int* src  = (const int*)d_in[8];
    const int* dst  = (const int*)d_in[9];
    float* out = (float*)d_out;

    // order chosen so the ncu capture slot (4th launch) lands on k_gemm_feat
    k_zero<<<(MP * NN + 255) / 256, 256>>>();
    k_hist<<<(MP * NE + 255) / 256, 256>>>(dst);
    k_scan<<<MP, 1024>>>();
    k_gemm_feat<<<dim3((NN + 127) / 128, DF / 128, MP), 256>>>(h, Wg, al, ar);
    k_scatter<<<(MP * NE + 255) / 256, 256>>>(src, dst);
    k_agg<<<dim3(NN, MP), 256>>>(bg);
    k_gemm_sem<<<(RTOT + 127) / 128, 256>>>(W1, b1, w2);
    k_beta<<<1, 1>>>();
    k_final<<<(NN * DF + 255) / 256, 256>>>(out);
}